// round 1
// baseline (speedup 1.0000x reference)
#include <cuda_runtime.h>
#include <math.h>
#include <stdint.h>

// ---------------------------------------------------------------------------
// Problem constants
// ---------------------------------------------------------------------------
#define HIDDEN      4096
#define NUM_HEADS   32
#define NUM_KV      8
#define HEAD_DIM    128
#define Q_SIZE      4096            // NUM_HEADS * HEAD_DIM
#define KV_SIZE     1024            // NUM_KV * HEAD_DIM
#define QKV_N       6144            // Q_SIZE + 2*KV_SIZE
#define BATCH       2
#define SEQ         2048
#define NTOK        (BATCH * SEQ)   // 4096

// Scratch (no cudaMalloc allowed — static device globals)
__device__ float g_qkv[(size_t)NTOK * QKV_N];    // ~100 MB
__device__ float g_attn[(size_t)NTOK * Q_SIZE];  // ~64 MB

// ---------------------------------------------------------------------------
// SGEMM: C[M,N] = A[M,K] @ B[K,N], row-major, all dims multiples of 128/8.
// 128x128 block tile, 8-deep K tile, 8x8 per thread, 256 threads.
// ---------------------------------------------------------------------------
#define BM 128
#define BN 128
#define BK 8
#define TM 8
#define TN 8

__global__ void __launch_bounds__(256)
sgemm_kernel(const float* __restrict__ A, const float* __restrict__ B,
             float* __restrict__ C, int M, int N, int K)
{
    __shared__ float As[BK][BM];
    __shared__ float Bs[BK][BN];

    const int tid  = threadIdx.x;
    const int cRow = blockIdx.y;   // M tile
    const int cCol = blockIdx.x;   // N tile

    const float* Ab = A + (size_t)cRow * BM * K;
    const float* Bb = B + (size_t)cCol * BN;

    // A tile loader: 128 rows x 8 cols, one float4 per thread
    const int aRow = tid >> 1;            // 0..127
    const int aCol = (tid & 1) * 4;       // 0 or 4
    // B tile loader: 8 rows x 128 cols, one float4 per thread
    const int bRow = tid >> 5;            // 0..7
    const int bCol = (tid & 31) * 4;      // 0..124

    const int tr = tid >> 4;              // 0..15 (row group)
    const int tc = tid & 15;              // 0..15 (col group)

    float acc[TM][TN];
    #pragma unroll
    for (int i = 0; i < TM; i++)
        #pragma unroll
        for (int j = 0; j < TN; j++) acc[i][j] = 0.0f;

    for (int k0 = 0; k0 < K; k0 += BK) {
        float4 av = *(const float4*)(Ab + (size_t)aRow * K + k0 + aCol);
        As[aCol + 0][aRow] = av.x;
        As[aCol + 1][aRow] = av.y;
        As[aCol + 2][aRow] = av.z;
        As[aCol + 3][aRow] = av.w;

        float4 bv = *(const float4*)(Bb + (size_t)(k0 + bRow) * N + bCol);
        *(float4*)(&Bs[bRow][bCol]) = bv;

        __syncthreads();

        #pragma unroll
        for (int k = 0; k < BK; k++) {
            float ra[TM], rb[TN];
            float4 a0 = *(const float4*)(&As[k][tr * TM]);
            float4 a1 = *(const float4*)(&As[k][tr * TM + 4]);
            float4 b0 = *(const float4*)(&Bs[k][tc * TN]);
            float4 b1 = *(const float4*)(&Bs[k][tc * TN + 4]);
            ra[0]=a0.x; ra[1]=a0.y; ra[2]=a0.z; ra[3]=a0.w;
            ra[4]=a1.x; ra[5]=a1.y; ra[6]=a1.z; ra[7]=a1.w;
            rb[0]=b0.x; rb[1]=b0.y; rb[2]=b0.z; rb[3]=b0.w;
            rb[4]=b1.x; rb[5]=b1.y; rb[6]=b1.z; rb[7]=b1.w;
            #pragma unroll
            for (int i = 0; i < TM; i++)
                #pragma unroll
                for (int j = 0; j < TN; j++)
                    acc[i][j] += ra[i] * rb[j];
        }
        __syncthreads();
    }

    #pragma unroll
    for (int i = 0; i < TM; i++) {
        float* Crow = C + (size_t)(cRow * BM + tr * TM + i) * N + cCol * BN + tc * TN;
        float4 v0 = make_float4(acc[i][0], acc[i][1], acc[i][2], acc[i][3]);
        float4 v1 = make_float4(acc[i][4], acc[i][5], acc[i][6], acc[i][7]);
        *(float4*)(Crow)     = v0;
        *(float4*)(Crow + 4) = v1;
    }
}

// ---------------------------------------------------------------------------
// RoPE in place on q (32 heads) and k (8 heads) inside the qkv buffer.
// One thread per (token, head, pair).  40 heads * 64 pairs per token.
// ---------------------------------------------------------------------------
__global__ void __launch_bounds__(256)
rope_kernel(const int* __restrict__ positions, float* __restrict__ qkv)
{
    int idx = blockIdx.x * blockDim.x + threadIdx.x;  // < NTOK*40*64
    int i  = idx & 63;              // pair index 0..63
    int hh = (idx >> 6) % 40;       // 0..31 = q head, 32..39 = kv head
    int t  = idx / (40 * 64);       // token

    float pos = (float)positions[t];
    // inv_freq = 10000^(-i/64) = 2^(-i * log2(10000)/64)
    float invf = exp2f(-(float)i * (13.287712379549449f / 64.0f));
    float ang  = pos * invf;
    float s, c;
    sincosf(ang, &s, &c);

    int base = (hh < 32) ? hh * HEAD_DIM : Q_SIZE + (hh - 32) * HEAD_DIM;
    float* p = qkv + (size_t)t * QKV_N + base;
    float x1 = p[i];
    float x2 = p[i + 64];
    p[i]      = x1 * c - x2 * s;
    p[i + 64] = x2 * c + x1 * s;
}

// ---------------------------------------------------------------------------
// Flash-style causal attention. One block = (q-tile of 64, head, batch).
// Q,K stored transposed in smem ([d][row]) for float4 inner loops.
// Streaming (online) softmax in fp32.
// ---------------------------------------------------------------------------
#define BQ   64
#define BKV  64
#define PADT 68     // row stride for Qt/Kt/Sc (over the 64-wide dim)
#define PADV 132    // row stride for Vs (over the 128-wide dim)

#define ATTN_SMEM_FLOATS (128*PADT + 128*PADT + 64*PADV + 64*PADT + 3*64)
#define ATTN_SMEM_BYTES  (ATTN_SMEM_FLOATS * 4)

__global__ void __launch_bounds__(256)
attn_kernel(const float* __restrict__ qkv, float* __restrict__ attn_out)
{
    extern __shared__ float sm[];
    float* Qt    = sm;                   // [128][PADT]  Q transposed
    float* Kt    = Qt + 128 * PADT;      // [128][PADT]  K transposed
    float* Vs    = Kt + 128 * PADT;      // [64][PADV]   V natural
    float* Sc    = Vs + 64 * PADV;       // [64][PADT]   scores / probs
    float* mrow  = Sc + 64 * PADT;       // [64] running max
    float* lrow  = mrow + 64;            // [64] running sum
    float* scrow = lrow + 64;            // [64] rescale factor

    const int qt  = blockIdx.x;          // q tile (0..31)
    const int h   = blockIdx.y;          // head  (0..31)
    const int b   = blockIdx.z;          // batch (0..1)
    const int tid = threadIdx.x;
    const int kvh = h >> 2;              // GQA group of 4

    const float scale = 0.08838834764831845f;  // 1/sqrt(128)

    const size_t tq0 = (size_t)b * SEQ + (size_t)qt * BQ;   // first q token
    const size_t tb0 = (size_t)b * SEQ;                     // batch token base
    const int koff = Q_SIZE + kvh * HEAD_DIM;
    const int voff = Q_SIZE + KV_SIZE + kvh * HEAD_DIM;

    // ---- load Q transposed (rows fixed per thread, d4 strided -> 2-way max)
    const int lr   = tid >> 2;     // row 0..63
    const int ld4l = tid & 3;      // low 2 bits of float4-chunk index
    {
        const float* qbase = qkv + (tq0 + lr) * QKV_N + h * HEAD_DIM;
        #pragma unroll
        for (int j = 0; j < 8; j++) {
            int d4 = ld4l + 4 * j;
            float4 v = *(const float4*)(qbase + d4 * 4);
            Qt[(d4 * 4 + 0) * PADT + lr] = v.x;
            Qt[(d4 * 4 + 1) * PADT + lr] = v.y;
            Qt[(d4 * 4 + 2) * PADT + lr] = v.z;
            Qt[(d4 * 4 + 3) * PADT + lr] = v.w;
        }
    }
    if (tid < 64) { mrow[tid] = -1e30f; lrow[tid] = 0.0f; }

    const int ty = tid >> 4;   // 0..15
    const int tx = tid & 15;   // 0..15

    float acc[4][8];
    #pragma unroll
    for (int i = 0; i < 4; i++)
        #pragma unroll
        for (int j = 0; j < 8; j++) acc[i][j] = 0.0f;

    for (int kt = 0; kt <= qt; kt++) {
        // ---- load K (transposed) and V (natural)
        {
            const float* kbase = qkv + (tb0 + (size_t)kt * BKV + lr) * QKV_N + koff;
            #pragma unroll
            for (int j = 0; j < 8; j++) {
                int d4 = ld4l + 4 * j;
                float4 v = *(const float4*)(kbase + d4 * 4);
                Kt[(d4 * 4 + 0) * PADT + lr] = v.x;
                Kt[(d4 * 4 + 1) * PADT + lr] = v.y;
                Kt[(d4 * 4 + 2) * PADT + lr] = v.z;
                Kt[(d4 * 4 + 3) * PADT + lr] = v.w;
            }
            #pragma unroll
            for (int j = 0; j < 8; j++) {
                int idx = tid + 256 * j;       // < 2048
                int vr  = idx >> 5;            // 0..63
                int c4  = idx & 31;            // 0..31
                float4 v = *(const float4*)(qkv + (tb0 + (size_t)kt * BKV + vr) * QKV_N
                                            + voff + c4 * 4);
                *(float4*)(Vs + vr * PADV + c4 * 4) = v;
            }
        }
        __syncthreads();

        // ---- phase 1: S = scale * Q @ K^T (+ causal mask on diagonal tile)
        {
            float sacc[4][4];
            #pragma unroll
            for (int i = 0; i < 4; i++)
                #pragma unroll
                for (int j = 0; j < 4; j++) sacc[i][j] = 0.0f;

            #pragma unroll 4
            for (int d = 0; d < 128; d++) {
                float4 qv = *(const float4*)(Qt + d * PADT + ty * 4);
                float4 kv = *(const float4*)(Kt + d * PADT + tx * 4);
                float rq[4] = {qv.x, qv.y, qv.z, qv.w};
                float rk[4] = {kv.x, kv.y, kv.z, kv.w};
                #pragma unroll
                for (int i = 0; i < 4; i++)
                    #pragma unroll
                    for (int j = 0; j < 4; j++)
                        sacc[i][j] += rq[i] * rk[j];
            }

            const int qg0 = qt * BQ + ty * 4;   // q pos (within seq)
            const int kg0 = kt * BKV + tx * 4;  // k pos
            const bool diag = (kt == qt);
            #pragma unroll
            for (int i = 0; i < 4; i++) {
                float4 out;
                float v0 = sacc[i][0] * scale;
                float v1 = sacc[i][1] * scale;
                float v2 = sacc[i][2] * scale;
                float v3 = sacc[i][3] * scale;
                if (diag) {
                    if (kg0 + 0 > qg0 + i) v0 = -1e30f;
                    if (kg0 + 1 > qg0 + i) v1 = -1e30f;
                    if (kg0 + 2 > qg0 + i) v2 = -1e30f;
                    if (kg0 + 3 > qg0 + i) v3 = -1e30f;
                }
                out = make_float4(v0, v1, v2, v3);
                *(float4*)(Sc + (ty * 4 + i) * PADT + tx * 4) = out;
            }
        }
        __syncthreads();

        // ---- phase 2: online softmax (4 threads per row)
        {
            const int pr = tid >> 2;       // row 0..63
            const int pq = tid & 3;        // col quarter
            float* srow = Sc + pr * PADT + pq * 16;

            float mloc = -1e30f;
            #pragma unroll
            for (int cc = 0; cc < 16; cc++) mloc = fmaxf(mloc, srow[cc]);
            mloc = fmaxf(mloc, __shfl_xor_sync(0xffffffffu, mloc, 1));
            mloc = fmaxf(mloc, __shfl_xor_sync(0xffffffffu, mloc, 2));

            float mprev = mrow[pr];
            float mnew  = fmaxf(mprev, mloc);

            float ssum = 0.0f;
            #pragma unroll
            for (int cc = 0; cc < 16; cc++) {
                float p = expf(srow[cc] - mnew);
                srow[cc] = p;
                ssum += p;
            }
            ssum += __shfl_xor_sync(0xffffffffu, ssum, 1);
            ssum += __shfl_xor_sync(0xffffffffu, ssum, 2);

            if (pq == 0) {
                float sc_ = expf(mprev - mnew);     // 0 on first tile
                scrow[pr] = sc_;
                lrow[pr]  = lrow[pr] * sc_ + ssum;
                mrow[pr]  = mnew;
            }
        }
        __syncthreads();

        // ---- phase 3: O = O * rescale + P @ V
        {
            float scl[4];
            #pragma unroll
            for (int i = 0; i < 4; i++) scl[i] = scrow[ty * 4 + i];
            #pragma unroll
            for (int i = 0; i < 4; i++)
                #pragma unroll
                for (int j = 0; j < 8; j++) acc[i][j] *= scl[i];

            #pragma unroll 4
            for (int k = 0; k < BKV; k++) {
                float pv[4];
                #pragma unroll
                for (int i = 0; i < 4; i++) pv[i] = Sc[(ty * 4 + i) * PADT + k];
                float4 v0 = *(const float4*)(Vs + k * PADV + tx * 8);
                float4 v1 = *(const float4*)(Vs + k * PADV + tx * 8 + 4);
                #pragma unroll
                for (int i = 0; i < 4; i++) {
                    acc[i][0] += pv[i] * v0.x;
                    acc[i][1] += pv[i] * v0.y;
                    acc[i][2] += pv[i] * v0.z;
                    acc[i][3] += pv[i] * v0.w;
                    acc[i][4] += pv[i] * v1.x;
                    acc[i][5] += pv[i] * v1.y;
                    acc[i][6] += pv[i] * v1.z;
                    acc[i][7] += pv[i] * v1.w;
                }
            }
        }
        __syncthreads();   // protect Kt/Vs/Sc for next tile's loads
    }

    // ---- epilogue: divide by l, write to attn buffer [tok][h*128+c]
    {
        float linv[4];
        #pragma unroll
        for (int i = 0; i < 4; i++) linv[i] = 1.0f / lrow[ty * 4 + i];
        #pragma unroll
        for (int i = 0; i < 4; i++) {
            float* orow = attn_out + (tq0 + ty * 4 + i) * (size_t)Q_SIZE
                          + h * HEAD_DIM + tx * 8;
            float4 v0 = make_float4(acc[i][0] * linv[i], acc[i][1] * linv[i],
                                    acc[i][2] * linv[i], acc[i][3] * linv[i]);
            float4 v1 = make_float4(acc[i][4] * linv[i], acc[i][5] * linv[i],
                                    acc[i][6] * linv[i], acc[i][7] * linv[i]);
            *(float4*)(orow)     = v0;
            *(float4*)(orow + 4) = v1;
        }
    }
}

// ---------------------------------------------------------------------------
// Launcher
// ---------------------------------------------------------------------------
extern "C" void kernel_launch(void* const* d_in, const int* in_sizes, int n_in,
                              void* d_out, int out_size)
{
    const int*   positions = (const int*)  d_in[0];
    const float* hidden    = (const float*)d_in[1];
    const float* w_qkv     = (const float*)d_in[2];
    const float* w_o       = (const float*)d_in[3];
    float*       out       = (float*)      d_out;

    float* qkvp  = nullptr;
    float* attnp = nullptr;
    cudaGetSymbolAddress((void**)&qkvp,  g_qkv);
    cudaGetSymbolAddress((void**)&attnp, g_attn);

    // 1) QKV projection: [NTOK, HIDDEN] @ [HIDDEN, QKV_N]
    {
        dim3 grid(QKV_N / BN, NTOK / BM);
        sgemm_kernel<<<grid, 256>>>(hidden, w_qkv, qkvp, NTOK, QKV_N, HIDDEN);
    }

    // 2) RoPE on q + k
    {
        int total = NTOK * 40 * 64;
        rope_kernel<<<total / 256, 256>>>(positions, qkvp);
    }

    // 3) Causal attention
    {
        cudaFuncSetAttribute(attn_kernel,
                             cudaFuncAttributeMaxDynamicSharedMemorySize,
                             ATTN_SMEM_BYTES);
        dim3 grid(SEQ / BQ, NUM_HEADS, BATCH);
        attn_kernel<<<grid, 256, ATTN_SMEM_BYTES>>>(qkvp, attnp);
    }

    // 4) Output projection: [NTOK, Q_SIZE] @ [Q_SIZE, HIDDEN]
    {
        dim3 grid(HIDDEN / BN, NTOK / BM);
        sgemm_kernel<<<grid, 256>>>(attnp, w_o, out, NTOK, HIDDEN, Q_SIZE);
    }
}

// round 2
// speedup vs baseline: 1.9489x; 1.9489x over previous
#include <cuda_runtime.h>
#include <math.h>
#include <stdint.h>

// ---------------------------------------------------------------------------
// Problem constants
// ---------------------------------------------------------------------------
#define HIDDEN      4096
#define NUM_HEADS   32
#define NUM_KV      8
#define HEAD_DIM    128
#define Q_SIZE      4096            // NUM_HEADS * HEAD_DIM
#define KV_SIZE     1024            // NUM_KV * HEAD_DIM
#define QKV_N       6144            // Q_SIZE + 2*KV_SIZE
#define BATCH       2
#define SEQ         2048
#define NTOK        (BATCH * SEQ)   // 4096

// Scratch (no cudaMalloc allowed — static device globals)
__device__ float g_qkv[(size_t)NTOK * QKV_N];    // ~100 MB
__device__ float g_attn[(size_t)NTOK * Q_SIZE];  // ~64 MB

// ---------------------------------------------------------------------------
// TF32 tensor-core GEMM: C[M,N] = A[M,K] @ B[K,N], row-major.
// Block tile 128x128, K-tile 16, 256 threads = 8 warps (2x4 warp grid),
// warp tile 64x32 via mma.sync.m16n8k8.tf32 (4 m-tiles x 4 n-tiles).
// Inputs rounded to tf32 (cvt.rna) when staged to smem.
// ---------------------------------------------------------------------------
#define GSA 20      // As row stride: [m][k], 16 + 4 pad (conflict-free frag reads)
#define GSB 136     // Bs row stride: [k][n], 128 + 8 pad (conflict-free)

__device__ __forceinline__ uint32_t f2tf32(float f) {
    uint32_t u;
    asm("cvt.rna.tf32.f32 %0, %1;" : "=r"(u) : "f"(f));
    return u;
}

__global__ void __launch_bounds__(256)
tf32_gemm_kernel(const float* __restrict__ A, const float* __restrict__ B,
                 float* __restrict__ C, int M, int N, int K)
{
    __shared__ float As[128 * GSA];   // [m][k]
    __shared__ float Bs[16 * GSB];    // [k][n]

    const int tid  = threadIdx.x;
    const int warp = tid >> 5;
    const int lane = tid & 31;
    const int g    = lane >> 2;      // groupID 0..7
    const int tig  = lane & 3;       // thread-in-group 0..3
    const int wm   = warp >> 2;      // 0..1
    const int wn   = warp & 3;       // 0..3
    const int mbase = wm * 64;
    const int nbase = wn * 32;

    const float* Ab = A + (size_t)blockIdx.y * 128 * K;
    const float* Bb = B + (size_t)blockIdx.x * 128;

    // loaders
    const int aRow = tid >> 2;          // 0..63 (two passes: +0, +64)
    const int aC4  = (tid & 3) * 4;     // k offset within tile
    const int bRow = tid >> 5;          // 0..7  (two passes: +0, +8)
    const int bCol = (tid & 31) * 4;

    float c[4][4][4];
    #pragma unroll
    for (int mt = 0; mt < 4; mt++)
        #pragma unroll
        for (int nt = 0; nt < 4; nt++)
            #pragma unroll
            for (int i = 0; i < 4; i++) c[mt][nt][i] = 0.0f;

    for (int k0 = 0; k0 < K; k0 += 16) {
        // stage A tile [128][16] -> As[m][k], tf32-rounded
        #pragma unroll
        for (int p = 0; p < 2; p++) {
            int r = aRow + p * 64;
            float4 v = *(const float4*)(Ab + (size_t)r * K + k0 + aC4);
            float4 t;
            t.x = __uint_as_float(f2tf32(v.x));
            t.y = __uint_as_float(f2tf32(v.y));
            t.z = __uint_as_float(f2tf32(v.z));
            t.w = __uint_as_float(f2tf32(v.w));
            *(float4*)(As + r * GSA + aC4) = t;
        }
        // stage B tile [16][128] -> Bs[k][n], tf32-rounded
        #pragma unroll
        for (int p = 0; p < 2; p++) {
            int r = bRow + p * 8;
            float4 v = *(const float4*)(Bb + (size_t)(k0 + r) * N + bCol);
            float4 t;
            t.x = __uint_as_float(f2tf32(v.x));
            t.y = __uint_as_float(f2tf32(v.y));
            t.z = __uint_as_float(f2tf32(v.z));
            t.w = __uint_as_float(f2tf32(v.w));
            *(float4*)(Bs + r * GSB + bCol) = t;
        }
        __syncthreads();

        #pragma unroll
        for (int kk = 0; kk < 16; kk += 8) {
            uint32_t a[4][4], b[4][2];
            #pragma unroll
            for (int mt = 0; mt < 4; mt++) {
                int r0 = (mbase + mt * 16 + g) * GSA + kk + tig;
                a[mt][0] = __float_as_uint(As[r0]);
                a[mt][1] = __float_as_uint(As[r0 + 8 * GSA]);
                a[mt][2] = __float_as_uint(As[r0 + 4]);
                a[mt][3] = __float_as_uint(As[r0 + 8 * GSA + 4]);
            }
            #pragma unroll
            for (int nt = 0; nt < 4; nt++) {
                int cn = nbase + nt * 8 + g;
                b[nt][0] = __float_as_uint(Bs[(kk + tig) * GSB + cn]);
                b[nt][1] = __float_as_uint(Bs[(kk + tig + 4) * GSB + cn]);
            }
            #pragma unroll
            for (int mt = 0; mt < 4; mt++)
                #pragma unroll
                for (int nt = 0; nt < 4; nt++)
                    asm volatile(
                        "mma.sync.aligned.m16n8k8.row.col.f32.tf32.tf32.f32 "
                        "{%0,%1,%2,%3}, {%4,%5,%6,%7}, {%8,%9}, {%0,%1,%2,%3};"
                        : "+f"(c[mt][nt][0]), "+f"(c[mt][nt][1]),
                          "+f"(c[mt][nt][2]), "+f"(c[mt][nt][3])
                        : "r"(a[mt][0]), "r"(a[mt][1]), "r"(a[mt][2]), "r"(a[mt][3]),
                          "r"(b[nt][0]), "r"(b[nt][1]));
        }
        __syncthreads();
    }

    // epilogue
    const int crow0 = blockIdx.y * 128 + mbase + g;
    const int ccol0 = blockIdx.x * 128 + nbase;
    #pragma unroll
    for (int mt = 0; mt < 4; mt++) {
        #pragma unroll
        for (int nt = 0; nt < 4; nt++) {
            float* p0 = C + (size_t)(crow0 + mt * 16) * N + ccol0 + nt * 8 + 2 * tig;
            float* p1 = p0 + 8 * (size_t)N;
            *(float2*)p0 = make_float2(c[mt][nt][0], c[mt][nt][1]);
            *(float2*)p1 = make_float2(c[mt][nt][2], c[mt][nt][3]);
        }
    }
}

// ---------------------------------------------------------------------------
// RoPE in place on q (32 heads) and k (8 heads) inside the qkv buffer.
// ---------------------------------------------------------------------------
__global__ void __launch_bounds__(256)
rope_kernel(const int* __restrict__ positions, float* __restrict__ qkv)
{
    int idx = blockIdx.x * blockDim.x + threadIdx.x;  // < NTOK*40*64
    int i  = idx & 63;              // pair index 0..63
    int hh = (idx >> 6) % 40;       // 0..31 = q head, 32..39 = kv head
    int t  = idx / (40 * 64);       // token

    float pos = (float)positions[t];
    float invf = exp2f(-(float)i * (13.287712379549449f / 64.0f));
    float ang  = pos * invf;
    float s, c;
    sincosf(ang, &s, &c);

    int base = (hh < 32) ? hh * HEAD_DIM : Q_SIZE + (hh - 32) * HEAD_DIM;
    float* p = qkv + (size_t)t * QKV_N + base;
    float x1 = p[i];
    float x2 = p[i + 64];
    p[i]      = x1 * c - x2 * s;
    p[i + 64] = x2 * c + x1 * s;
}

// ---------------------------------------------------------------------------
// Flash-style causal attention (fp32 SIMT, unchanged from round 1).
// ---------------------------------------------------------------------------
#define BQ   64
#define BKV  64
#define PADT 68
#define PADV 132

#define ATTN_SMEM_FLOATS (128*PADT + 128*PADT + 64*PADV + 64*PADT + 3*64)
#define ATTN_SMEM_BYTES  (ATTN_SMEM_FLOATS * 4)

__global__ void __launch_bounds__(256)
attn_kernel(const float* __restrict__ qkv, float* __restrict__ attn_out)
{
    extern __shared__ float sm[];
    float* Qt    = sm;
    float* Kt    = Qt + 128 * PADT;
    float* Vs    = Kt + 128 * PADT;
    float* Sc    = Vs + 64 * PADV;
    float* mrow  = Sc + 64 * PADT;
    float* lrow  = mrow + 64;
    float* scrow = lrow + 64;

    const int qt  = blockIdx.x;
    const int h   = blockIdx.y;
    const int b   = blockIdx.z;
    const int tid = threadIdx.x;
    const int kvh = h >> 2;

    const float scale = 0.08838834764831845f;

    const size_t tq0 = (size_t)b * SEQ + (size_t)qt * BQ;
    const size_t tb0 = (size_t)b * SEQ;
    const int koff = Q_SIZE + kvh * HEAD_DIM;
    const int voff = Q_SIZE + KV_SIZE + kvh * HEAD_DIM;

    const int lr   = tid >> 2;
    const int ld4l = tid & 3;
    {
        const float* qbase = qkv + (tq0 + lr) * QKV_N + h * HEAD_DIM;
        #pragma unroll
        for (int j = 0; j < 8; j++) {
            int d4 = ld4l + 4 * j;
            float4 v = *(const float4*)(qbase + d4 * 4);
            Qt[(d4 * 4 + 0) * PADT + lr] = v.x;
            Qt[(d4 * 4 + 1) * PADT + lr] = v.y;
            Qt[(d4 * 4 + 2) * PADT + lr] = v.z;
            Qt[(d4 * 4 + 3) * PADT + lr] = v.w;
        }
    }
    if (tid < 64) { mrow[tid] = -1e30f; lrow[tid] = 0.0f; }

    const int ty = tid >> 4;
    const int tx = tid & 15;

    float acc[4][8];
    #pragma unroll
    for (int i = 0; i < 4; i++)
        #pragma unroll
        for (int j = 0; j < 8; j++) acc[i][j] = 0.0f;

    for (int kt = 0; kt <= qt; kt++) {
        {
            const float* kbase = qkv + (tb0 + (size_t)kt * BKV + lr) * QKV_N + koff;
            #pragma unroll
            for (int j = 0; j < 8; j++) {
                int d4 = ld4l + 4 * j;
                float4 v = *(const float4*)(kbase + d4 * 4);
                Kt[(d4 * 4 + 0) * PADT + lr] = v.x;
                Kt[(d4 * 4 + 1) * PADT + lr] = v.y;
                Kt[(d4 * 4 + 2) * PADT + lr] = v.z;
                Kt[(d4 * 4 + 3) * PADT + lr] = v.w;
            }
            #pragma unroll
            for (int j = 0; j < 8; j++) {
                int idx = tid + 256 * j;
                int vr  = idx >> 5;
                int c4  = idx & 31;
                float4 v = *(const float4*)(qkv + (tb0 + (size_t)kt * BKV + vr) * QKV_N
                                            + voff + c4 * 4);
                *(float4*)(Vs + vr * PADV + c4 * 4) = v;
            }
        }
        __syncthreads();

        {
            float sacc[4][4];
            #pragma unroll
            for (int i = 0; i < 4; i++)
                #pragma unroll
                for (int j = 0; j < 4; j++) sacc[i][j] = 0.0f;

            #pragma unroll 4
            for (int d = 0; d < 128; d++) {
                float4 qv = *(const float4*)(Qt + d * PADT + ty * 4);
                float4 kv = *(const float4*)(Kt + d * PADT + tx * 4);
                float rq[4] = {qv.x, qv.y, qv.z, qv.w};
                float rk[4] = {kv.x, kv.y, kv.z, kv.w};
                #pragma unroll
                for (int i = 0; i < 4; i++)
                    #pragma unroll
                    for (int j = 0; j < 4; j++)
                        sacc[i][j] += rq[i] * rk[j];
            }

            const int qg0 = qt * BQ + ty * 4;
            const int kg0 = kt * BKV + tx * 4;
            const bool diag = (kt == qt);
            #pragma unroll
            for (int i = 0; i < 4; i++) {
                float v0 = sacc[i][0] * scale;
                float v1 = sacc[i][1] * scale;
                float v2 = sacc[i][2] * scale;
                float v3 = sacc[i][3] * scale;
                if (diag) {
                    if (kg0 + 0 > qg0 + i) v0 = -1e30f;
                    if (kg0 + 1 > qg0 + i) v1 = -1e30f;
                    if (kg0 + 2 > qg0 + i) v2 = -1e30f;
                    if (kg0 + 3 > qg0 + i) v3 = -1e30f;
                }
                *(float4*)(Sc + (ty * 4 + i) * PADT + tx * 4) =
                    make_float4(v0, v1, v2, v3);
            }
        }
        __syncthreads();

        {
            const int pr = tid >> 2;
            const int pq = tid & 3;
            float* srow = Sc + pr * PADT + pq * 16;

            float mloc = -1e30f;
            #pragma unroll
            for (int cc = 0; cc < 16; cc++) mloc = fmaxf(mloc, srow[cc]);
            mloc = fmaxf(mloc, __shfl_xor_sync(0xffffffffu, mloc, 1));
            mloc = fmaxf(mloc, __shfl_xor_sync(0xffffffffu, mloc, 2));

            float mprev = mrow[pr];
            float mnew  = fmaxf(mprev, mloc);

            float ssum = 0.0f;
            #pragma unroll
            for (int cc = 0; cc < 16; cc++) {
                float p = expf(srow[cc] - mnew);
                srow[cc] = p;
                ssum += p;
            }
            ssum += __shfl_xor_sync(0xffffffffu, ssum, 1);
            ssum += __shfl_xor_sync(0xffffffffu, ssum, 2);

            if (pq == 0) {
                float sc_ = expf(mprev - mnew);
                scrow[pr] = sc_;
                lrow[pr]  = lrow[pr] * sc_ + ssum;
                mrow[pr]  = mnew;
            }
        }
        __syncthreads();

        {
            float scl[4];
            #pragma unroll
            for (int i = 0; i < 4; i++) scl[i] = scrow[ty * 4 + i];
            #pragma unroll
            for (int i = 0; i < 4; i++)
                #pragma unroll
                for (int j = 0; j < 8; j++) acc[i][j] *= scl[i];

            #pragma unroll 4
            for (int k = 0; k < BKV; k++) {
                float pv[4];
                #pragma unroll
                for (int i = 0; i < 4; i++) pv[i] = Sc[(ty * 4 + i) * PADT + k];
                float4 v0 = *(const float4*)(Vs + k * PADV + tx * 8);
                float4 v1 = *(const float4*)(Vs + k * PADV + tx * 8 + 4);
                #pragma unroll
                for (int i = 0; i < 4; i++) {
                    acc[i][0] += pv[i] * v0.x;
                    acc[i][1] += pv[i] * v0.y;
                    acc[i][2] += pv[i] * v0.z;
                    acc[i][3] += pv[i] * v0.w;
                    acc[i][4] += pv[i] * v1.x;
                    acc[i][5] += pv[i] * v1.y;
                    acc[i][6] += pv[i] * v1.z;
                    acc[i][7] += pv[i] * v1.w;
                }
            }
        }
        __syncthreads();
    }

    {
        float linv[4];
        #pragma unroll
        for (int i = 0; i < 4; i++) linv[i] = 1.0f / lrow[ty * 4 + i];
        #pragma unroll
        for (int i = 0; i < 4; i++) {
            float* orow = attn_out + (tq0 + ty * 4 + i) * (size_t)Q_SIZE
                          + h * HEAD_DIM + tx * 8;
            *(float4*)(orow)     = make_float4(acc[i][0] * linv[i], acc[i][1] * linv[i],
                                               acc[i][2] * linv[i], acc[i][3] * linv[i]);
            *(float4*)(orow + 4) = make_float4(acc[i][4] * linv[i], acc[i][5] * linv[i],
                                               acc[i][6] * linv[i], acc[i][7] * linv[i]);
        }
    }
}

// ---------------------------------------------------------------------------
// Launcher
// ---------------------------------------------------------------------------
extern "C" void kernel_launch(void* const* d_in, const int* in_sizes, int n_in,
                              void* d_out, int out_size)
{
    const int*   positions = (const int*)  d_in[0];
    const float* hidden    = (const float*)d_in[1];
    const float* w_qkv     = (const float*)d_in[2];
    const float* w_o       = (const float*)d_in[3];
    float*       out       = (float*)      d_out;

    float* qkvp  = nullptr;
    float* attnp = nullptr;
    cudaGetSymbolAddress((void**)&qkvp,  g_qkv);
    cudaGetSymbolAddress((void**)&attnp, g_attn);

    // 1) QKV projection: [NTOK, HIDDEN] @ [HIDDEN, QKV_N]  (tf32 tensor cores)
    {
        dim3 grid(QKV_N / 128, NTOK / 128);
        tf32_gemm_kernel<<<grid, 256>>>(hidden, w_qkv, qkvp, NTOK, QKV_N, HIDDEN);
    }

    // 2) RoPE on q + k
    {
        int total = NTOK * 40 * 64;
        rope_kernel<<<total / 256, 256>>>(positions, qkvp);
    }

    // 3) Causal attention
    {
        cudaFuncSetAttribute(attn_kernel,
                             cudaFuncAttributeMaxDynamicSharedMemorySize,
                             ATTN_SMEM_BYTES);
        dim3 grid(SEQ / BQ, NUM_HEADS, BATCH);
        attn_kernel<<<grid, 256, ATTN_SMEM_BYTES>>>(qkvp, attnp);
    }

    // 4) Output projection: [NTOK, Q_SIZE] @ [Q_SIZE, HIDDEN]  (tf32 tensor cores)
    {
        dim3 grid(HIDDEN / 128, NTOK / 128);
        tf32_gemm_kernel<<<grid, 256>>>(attnp, w_o, out, NTOK, HIDDEN, Q_SIZE);
    }
}

// round 3
// speedup vs baseline: 2.9790x; 1.5285x over previous
#include <cuda_runtime.h>
#include <math.h>
#include <stdint.h>

// ---------------------------------------------------------------------------
// Problem constants
// ---------------------------------------------------------------------------
#define HIDDEN      4096
#define NUM_HEADS   32
#define NUM_KV      8
#define HEAD_DIM    128
#define Q_SIZE      4096
#define KV_SIZE     1024
#define QKV_N       6144
#define BATCH       2
#define SEQ         2048
#define NTOK        (BATCH * SEQ)

__device__ float g_qkv[(size_t)NTOK * QKV_N];
__device__ float g_attn[(size_t)NTOK * Q_SIZE];

__device__ __forceinline__ uint32_t f2tf32(float f) {
    uint32_t u;
    asm("cvt.rna.tf32.f32 %0, %1;" : "=r"(u) : "f"(f));
    return u;
}

__device__ __forceinline__ void mma_tf32(float c[4], const uint32_t a[4],
                                         uint32_t b0, uint32_t b1) {
    asm volatile(
        "mma.sync.aligned.m16n8k8.row.col.f32.tf32.tf32.f32 "
        "{%0,%1,%2,%3}, {%4,%5,%6,%7}, {%8,%9}, {%0,%1,%2,%3};"
        : "+f"(c[0]), "+f"(c[1]), "+f"(c[2]), "+f"(c[3])
        : "r"(a[0]), "r"(a[1]), "r"(a[2]), "r"(a[3]), "r"(b0), "r"(b1));
}

// ---------------------------------------------------------------------------
// TF32 tensor-core GEMM (unchanged from round 2)
// ---------------------------------------------------------------------------
#define GSA 20
#define GSB 136

__global__ void __launch_bounds__(256)
tf32_gemm_kernel(const float* __restrict__ A, const float* __restrict__ B,
                 float* __restrict__ C, int M, int N, int K)
{
    __shared__ float As[128 * GSA];
    __shared__ float Bs[16 * GSB];

    const int tid  = threadIdx.x;
    const int warp = tid >> 5;
    const int lane = tid & 31;
    const int g    = lane >> 2;
    const int tig  = lane & 3;
    const int wm   = warp >> 2;
    const int wn   = warp & 3;
    const int mbase = wm * 64;
    const int nbase = wn * 32;

    const float* Ab = A + (size_t)blockIdx.y * 128 * K;
    const float* Bb = B + (size_t)blockIdx.x * 128;

    const int aRow = tid >> 2;
    const int aC4  = (tid & 3) * 4;
    const int bRow = tid >> 5;
    const int bCol = (tid & 31) * 4;

    float c[4][4][4];
    #pragma unroll
    for (int mt = 0; mt < 4; mt++)
        #pragma unroll
        for (int nt = 0; nt < 4; nt++)
            #pragma unroll
            for (int i = 0; i < 4; i++) c[mt][nt][i] = 0.0f;

    for (int k0 = 0; k0 < K; k0 += 16) {
        #pragma unroll
        for (int p = 0; p < 2; p++) {
            int r = aRow + p * 64;
            float4 v = *(const float4*)(Ab + (size_t)r * K + k0 + aC4);
            float4 t;
            t.x = __uint_as_float(f2tf32(v.x));
            t.y = __uint_as_float(f2tf32(v.y));
            t.z = __uint_as_float(f2tf32(v.z));
            t.w = __uint_as_float(f2tf32(v.w));
            *(float4*)(As + r * GSA + aC4) = t;
        }
        #pragma unroll
        for (int p = 0; p < 2; p++) {
            int r = bRow + p * 8;
            float4 v = *(const float4*)(Bb + (size_t)(k0 + r) * N + bCol);
            float4 t;
            t.x = __uint_as_float(f2tf32(v.x));
            t.y = __uint_as_float(f2tf32(v.y));
            t.z = __uint_as_float(f2tf32(v.z));
            t.w = __uint_as_float(f2tf32(v.w));
            *(float4*)(Bs + r * GSB + bCol) = t;
        }
        __syncthreads();

        #pragma unroll
        for (int kk = 0; kk < 16; kk += 8) {
            uint32_t a[4][4], b[4][2];
            #pragma unroll
            for (int mt = 0; mt < 4; mt++) {
                int r0 = (mbase + mt * 16 + g) * GSA + kk + tig;
                a[mt][0] = __float_as_uint(As[r0]);
                a[mt][1] = __float_as_uint(As[r0 + 8 * GSA]);
                a[mt][2] = __float_as_uint(As[r0 + 4]);
                a[mt][3] = __float_as_uint(As[r0 + 8 * GSA + 4]);
            }
            #pragma unroll
            for (int nt = 0; nt < 4; nt++) {
                int cn = nbase + nt * 8 + g;
                b[nt][0] = __float_as_uint(Bs[(kk + tig) * GSB + cn]);
                b[nt][1] = __float_as_uint(Bs[(kk + tig + 4) * GSB + cn]);
            }
            #pragma unroll
            for (int mt = 0; mt < 4; mt++)
                #pragma unroll
                for (int nt = 0; nt < 4; nt++)
                    mma_tf32(c[mt][nt], a[mt], b[nt][0], b[nt][1]);
        }
        __syncthreads();
    }

    const int crow0 = blockIdx.y * 128 + mbase + g;
    const int ccol0 = blockIdx.x * 128 + nbase;
    #pragma unroll
    for (int mt = 0; mt < 4; mt++) {
        #pragma unroll
        for (int nt = 0; nt < 4; nt++) {
            float* p0 = C + (size_t)(crow0 + mt * 16) * N + ccol0 + nt * 8 + 2 * tig;
            float* p1 = p0 + 8 * (size_t)N;
            *(float2*)p0 = make_float2(c[mt][nt][0], c[mt][nt][1]);
            *(float2*)p1 = make_float2(c[mt][nt][2], c[mt][nt][3]);
        }
    }
}

// ---------------------------------------------------------------------------
// RoPE (unchanged)
// ---------------------------------------------------------------------------
__global__ void __launch_bounds__(256)
rope_kernel(const int* __restrict__ positions, float* __restrict__ qkv)
{
    int idx = blockIdx.x * blockDim.x + threadIdx.x;
    int i  = idx & 63;
    int hh = (idx >> 6) % 40;
    int t  = idx / (40 * 64);

    float pos = (float)positions[t];
    float invf = exp2f(-(float)i * (13.287712379549449f / 64.0f));
    float ang  = pos * invf;
    float s, c;
    sincosf(ang, &s, &c);

    int base = (hh < 32) ? hh * HEAD_DIM : Q_SIZE + (hh - 32) * HEAD_DIM;
    float* p = qkv + (size_t)t * QKV_N + base;
    float x1 = p[i];
    float x2 = p[i + 64];
    p[i]      = x1 * c - x2 * s;
    p[i + 64] = x2 * c + x1 * s;
}

// ---------------------------------------------------------------------------
// FlashAttention-2 style causal attention with tf32 mma.
// Block: 128 q-rows x (head, batch). 8 warps, warp = one 16-row m-tile.
// KV tile = 64. smem strides chosen for conflict-free fragment LDS.
// ---------------------------------------------------------------------------
#define AQ   128
#define AKV  64
#define QS_S 132   // Qs [128][132]
#define KS_S 132   // Ks [64][132]
#define VT_S 68    // Vt [128][68]  (V transposed: [d][key])
#define PS_S 68    // Ps [128][68]

#define ATTN_SMEM_FLOATS (128*QS_S + 64*KS_S + 128*VT_S + 128*PS_S)
#define ATTN_SMEM_BYTES  (ATTN_SMEM_FLOATS * 4)

__global__ void __launch_bounds__(256, 1)
attn_mma_kernel(const float* __restrict__ qkv, float* __restrict__ attn_out)
{
    extern __shared__ float sm[];
    float* Qs = sm;                      // [128][QS_S]
    float* Ks = Qs + 128 * QS_S;         // [64][KS_S]
    float* Vt = Ks + 64 * KS_S;          // [128][VT_S]
    float* Ps = Vt + 128 * VT_S;         // [128][PS_S]

    const int qt   = blockIdx.x;         // 0..15
    const int h    = blockIdx.y;
    const int b    = blockIdx.z;
    const int tid  = threadIdx.x;
    const int warp = tid >> 5;
    const int lane = tid & 31;
    const int g    = lane >> 2;
    const int tig  = lane & 3;
    const int woff = warp * 16;
    const int kvh  = h >> 2;

    const size_t tq0 = (size_t)b * SEQ + (size_t)qt * AQ;
    const size_t tb0 = (size_t)b * SEQ;
    const int koff = Q_SIZE + kvh * HEAD_DIM;
    const int voff = Q_SIZE + KV_SIZE + kvh * HEAD_DIM;
    const float scale = 0.08838834764831845f;   // 1/sqrt(128)

    // ---- load Q (scaled + tf32-rounded), coalesced
    #pragma unroll
    for (int it = 0; it < 16; it++) {
        int idx = tid + 256 * it;          // < 4096
        int r   = idx >> 5;
        int c4  = (idx & 31) * 4;
        float4 v = *(const float4*)(qkv + (tq0 + r) * QKV_N + h * HEAD_DIM + c4);
        float4 t;
        t.x = __uint_as_float(f2tf32(v.x * scale));
        t.y = __uint_as_float(f2tf32(v.y * scale));
        t.z = __uint_as_float(f2tf32(v.z * scale));
        t.w = __uint_as_float(f2tf32(v.w * scale));
        *(float4*)(Qs + r * QS_S + c4) = t;
    }

    float o[16][4];
    #pragma unroll
    for (int dt = 0; dt < 16; dt++)
        #pragma unroll
        for (int i = 0; i < 4; i++) o[dt][i] = 0.0f;

    float mA = -1e30f, mB = -1e30f, lA = 0.0f, lB = 0.0f;
    const int rowbase = qt * AQ + woff;    // warp's first global q row
    const int rowA = rowbase + g;          // this thread's rows
    const int rowB = rowA + 8;

    const int ktmax = 2 * qt + 1;
    for (int kt = 0; kt <= ktmax; kt++) {
        // ---- load K tile [64][128] tf32, coalesced
        #pragma unroll
        for (int it = 0; it < 8; it++) {
            int idx = tid + 256 * it;      // < 2048
            int r   = idx >> 5;
            int c4  = (idx & 31) * 4;
            float4 v = *(const float4*)(qkv + (tb0 + (size_t)kt * AKV + r) * QKV_N
                                        + koff + c4);
            float4 t;
            t.x = __uint_as_float(f2tf32(v.x));
            t.y = __uint_as_float(f2tf32(v.y));
            t.z = __uint_as_float(f2tf32(v.z));
            t.w = __uint_as_float(f2tf32(v.w));
            *(float4*)(Ks + r * KS_S + c4) = t;
        }
        // ---- load V transposed -> Vt[d][key] (conflict-free stores)
        #pragma unroll
        for (int it = 0; it < 8; it++) {
            int idx = tid + 256 * it;      // < 2048
            int vr  = idx & 63;            // key
            int c4  = (idx >> 6) * 4;      // d chunk
            float4 v = *(const float4*)(qkv + (tb0 + (size_t)kt * AKV + vr) * QKV_N
                                        + voff + c4);
            Vt[(c4 + 0) * VT_S + vr] = __uint_as_float(f2tf32(v.x));
            Vt[(c4 + 1) * VT_S + vr] = __uint_as_float(f2tf32(v.y));
            Vt[(c4 + 2) * VT_S + vr] = __uint_as_float(f2tf32(v.z));
            Vt[(c4 + 3) * VT_S + vr] = __uint_as_float(f2tf32(v.w));
        }
        __syncthreads();

        const bool active = (kt * AKV <= rowbase + 15);  // tile not fully above diag
        if (active) {
            // ---- S = Q @ K^T  (16 x 64 per warp)
            float s[8][4];
            #pragma unroll
            for (int nt = 0; nt < 8; nt++)
                #pragma unroll
                for (int i = 0; i < 4; i++) s[nt][i] = 0.0f;

            #pragma unroll
            for (int kk = 0; kk < 128; kk += 8) {
                uint32_t a[4];
                const float* qp = Qs + (woff + g) * QS_S + kk + tig;
                a[0] = __float_as_uint(qp[0]);
                a[1] = __float_as_uint(qp[8 * QS_S]);
                a[2] = __float_as_uint(qp[4]);
                a[3] = __float_as_uint(qp[8 * QS_S + 4]);
                #pragma unroll
                for (int nt = 0; nt < 8; nt++) {
                    const float* kp = Ks + (nt * 8 + g) * KS_S + kk + tig;
                    mma_tf32(s[nt], a, __float_as_uint(kp[0]),
                                       __float_as_uint(kp[4]));
                }
            }

            // ---- causal mask (only possible near the diagonal)
            if (kt * AKV + 63 > rowbase) {
                #pragma unroll
                for (int nt = 0; nt < 8; nt++) {
                    int col = kt * AKV + nt * 8 + 2 * tig;
                    if (col     > rowA) s[nt][0] = -1e30f;
                    if (col + 1 > rowA) s[nt][1] = -1e30f;
                    if (col     > rowB) s[nt][2] = -1e30f;
                    if (col + 1 > rowB) s[nt][3] = -1e30f;
                }
            }

            // ---- online softmax in accumulator layout
            float mAl = -1e30f, mBl = -1e30f;
            #pragma unroll
            for (int nt = 0; nt < 8; nt++) {
                mAl = fmaxf(mAl, fmaxf(s[nt][0], s[nt][1]));
                mBl = fmaxf(mBl, fmaxf(s[nt][2], s[nt][3]));
            }
            mAl = fmaxf(mAl, __shfl_xor_sync(0xffffffffu, mAl, 1));
            mAl = fmaxf(mAl, __shfl_xor_sync(0xffffffffu, mAl, 2));
            mBl = fmaxf(mBl, __shfl_xor_sync(0xffffffffu, mBl, 1));
            mBl = fmaxf(mBl, __shfl_xor_sync(0xffffffffu, mBl, 2));

            float mAn = fmaxf(mA, mAl);
            float mBn = fmaxf(mB, mBl);
            float fA  = __expf(mA - mAn);
            float fB  = __expf(mB - mBn);

            float sumA = 0.0f, sumB = 0.0f;
            #pragma unroll
            for (int nt = 0; nt < 8; nt++) {
                s[nt][0] = __expf(s[nt][0] - mAn);
                s[nt][1] = __expf(s[nt][1] - mAn);
                s[nt][2] = __expf(s[nt][2] - mBn);
                s[nt][3] = __expf(s[nt][3] - mBn);
                sumA += s[nt][0] + s[nt][1];
                sumB += s[nt][2] + s[nt][3];
            }
            sumA += __shfl_xor_sync(0xffffffffu, sumA, 1);
            sumA += __shfl_xor_sync(0xffffffffu, sumA, 2);
            sumB += __shfl_xor_sync(0xffffffffu, sumB, 1);
            sumB += __shfl_xor_sync(0xffffffffu, sumB, 2);

            lA = lA * fA + sumA;  mA = mAn;
            lB = lB * fB + sumB;  mB = mBn;

            #pragma unroll
            for (int dt = 0; dt < 16; dt++) {
                o[dt][0] *= fA;  o[dt][1] *= fA;
                o[dt][2] *= fB;  o[dt][3] *= fB;
            }

            // ---- stage P to smem (tf32) for A-fragment reads
            #pragma unroll
            for (int nt = 0; nt < 8; nt++) {
                float* pA = Ps + (woff + g) * PS_S + nt * 8 + 2 * tig;
                float* pB = pA + 8 * PS_S;
                *(float2*)pA = make_float2(__uint_as_float(f2tf32(s[nt][0])),
                                           __uint_as_float(f2tf32(s[nt][1])));
                *(float2*)pB = make_float2(__uint_as_float(f2tf32(s[nt][2])),
                                           __uint_as_float(f2tf32(s[nt][3])));
            }
            __syncwarp();

            // ---- O += P @ V   (16 x 128 per warp)
            #pragma unroll
            for (int kk = 0; kk < 64; kk += 8) {
                uint32_t a[4];
                const float* pp = Ps + (woff + g) * PS_S + kk + tig;
                a[0] = __float_as_uint(pp[0]);
                a[1] = __float_as_uint(pp[8 * PS_S]);
                a[2] = __float_as_uint(pp[4]);
                a[3] = __float_as_uint(pp[8 * PS_S + 4]);
                #pragma unroll
                for (int dt = 0; dt < 16; dt++) {
                    const float* vp = Vt + (dt * 8 + g) * VT_S + kk + tig;
                    mma_tf32(o[dt], a, __float_as_uint(vp[0]),
                                       __float_as_uint(vp[4]));
                }
            }
        }
        __syncthreads();   // protect Ks/Vt for next tile
    }

    // ---- epilogue
    const float liA = 1.0f / lA;
    const float liB = 1.0f / lB;
    #pragma unroll
    for (int dt = 0; dt < 16; dt++) {
        float* pA = attn_out + (tq0 + woff + g) * (size_t)Q_SIZE
                    + h * HEAD_DIM + dt * 8 + 2 * tig;
        float* pB = pA + 8 * (size_t)Q_SIZE;
        *(float2*)pA = make_float2(o[dt][0] * liA, o[dt][1] * liA);
        *(float2*)pB = make_float2(o[dt][2] * liB, o[dt][3] * liB);
    }
}

// ---------------------------------------------------------------------------
// Launcher
// ---------------------------------------------------------------------------
extern "C" void kernel_launch(void* const* d_in, const int* in_sizes, int n_in,
                              void* d_out, int out_size)
{
    const int*   positions = (const int*)  d_in[0];
    const float* hidden    = (const float*)d_in[1];
    const float* w_qkv     = (const float*)d_in[2];
    const float* w_o       = (const float*)d_in[3];
    float*       out       = (float*)      d_out;

    float* qkvp  = nullptr;
    float* attnp = nullptr;
    cudaGetSymbolAddress((void**)&qkvp,  g_qkv);
    cudaGetSymbolAddress((void**)&attnp, g_attn);

    // 1) QKV projection
    {
        dim3 grid(QKV_N / 128, NTOK / 128);
        tf32_gemm_kernel<<<grid, 256>>>(hidden, w_qkv, qkvp, NTOK, QKV_N, HIDDEN);
    }

    // 2) RoPE
    {
        int total = NTOK * 40 * 64;
        rope_kernel<<<total / 256, 256>>>(positions, qkvp);
    }

    // 3) Causal attention (tf32 mma)
    {
        cudaFuncSetAttribute(attn_mma_kernel,
                             cudaFuncAttributeMaxDynamicSharedMemorySize,
                             ATTN_SMEM_BYTES);
        dim3 grid(SEQ / AQ, NUM_HEADS, BATCH);
        attn_mma_kernel<<<grid, 256, ATTN_SMEM_BYTES>>>(qkvp, attnp);
    }

    // 4) Output projection
    {
        dim3 grid(HIDDEN / 128, NTOK / 128);
        tf32_gemm_kernel<<<grid, 256>>>(attnp, w_o, out, NTOK, HIDDEN, Q_SIZE);
    }
}